// round 1
// baseline (speedup 1.0000x reference)
#include <cuda_runtime.h>
#include <cuda_bf16.h>

#define NN 50000
#define NE 800000
#define NG 128
#define D  64
#define NL 4
#define BN_EPS 1e-5f

#define TPB 512
#define WPB 16
#define GRID1 296

// ---------------- device scratch (no allocations allowed) ----------------
__device__ int   g_deg[NN];
__device__ int   g_off[NN + 1];
__device__ int   g_cur[NN];
__device__ int   g_esrc[NE];
__device__ float g_ew[NE];
__device__ __align__(16) float g_h[NN * D];   // node features (layer output)
__device__ __align__(16) float g_t[NN * D];   // intermediate t / r buffer
__device__ float g_stats[NL * 4 * D];         // [l][sum1,sq1,sum2,sq2][64]
__device__ float g_pool[(NL + 1) * NG * D];   // pooled per-graph features
__device__ int   g_gstart[NG + 1];

// ---------------- init: zero degree + stats ----------------
__global__ void k_init()
{
    int i = blockIdx.x * blockDim.x + threadIdx.x;
    if (i < NN) g_deg[i] = 0;
    if (i < NL * 4 * D) g_stats[i] = 0.f;
}

// ---------------- CSR build ----------------
__global__ void k_hist(const int* __restrict__ dst)
{
    int e = blockIdx.x * blockDim.x + threadIdx.x;
    if (e < NE) atomicAdd(&g_deg[dst[e]], 1);
}

__global__ void k_scan()
{
    __shared__ int part[1024];
    const int t = threadIdx.x;
    const int CH = (NN + 1023) / 1024;   // 49
    const int base = t * CH;
    int s = 0;
    for (int i = 0; i < CH; i++) {
        int n = base + i;
        if (n < NN) s += g_deg[n];
    }
    part[t] = s;
    __syncthreads();
    // Hillis-Steele inclusive scan
    for (int off = 1; off < 1024; off <<= 1) {
        int v = (t >= off) ? part[t - off] : 0;
        __syncthreads();
        part[t] += v;
        __syncthreads();
    }
    int run = (t == 0) ? 0 : part[t - 1];
    for (int i = 0; i < CH; i++) {
        int n = base + i;
        if (n < NN) {
            g_off[n] = run;
            g_cur[n] = run;
            run += g_deg[n];
        }
    }
    if (t == 1023) g_off[NN] = part[1023];
}

__global__ void k_scatter(const int* __restrict__ src, const int* __restrict__ dst,
                          const float* __restrict__ w)
{
    int e = blockIdx.x * blockDim.x + threadIdx.x;
    if (e < NE) {
        int d = dst[e];
        int p = atomicAdd(&g_cur[d], 1);
        g_esrc[p] = src[e];
        g_ew[p]   = w[e];
    }
}

// ---------------- graph boundaries (graph_ids sorted) ----------------
__global__ void k_gstart(const int* __restrict__ gids)
{
    int g = threadIdx.x;
    if (g > NG) return;
    if (g == NG) { g_gstart[NG] = NN; return; }
    int lo = 0, hi = NN;
    while (lo < hi) {
        int m = (lo + hi) >> 1;
        if (gids[m] < g) lo = m + 1; else hi = m;
    }
    g_gstart[g] = lo;
}

// ---------------- layer stage 1: aggregate + GEMM1 + stats ----------------
__global__ __launch_bounds__(TPB) void k_layer1(
    const float* __restrict__ x, int l,
    const float* __restrict__ W1l, const float* __restrict__ b1l,
    const float* __restrict__ epsv)
{
    __shared__ float sW[D * D];
    __shared__ float srow[WPB][D];
    __shared__ float s_sum[D];
    __shared__ float s_sq[D];

    const float* hin = (l == 0) ? x : g_h;

    for (int i = threadIdx.x; i < D * D; i += TPB) sW[i] = W1l[i];
    if (threadIdx.x < D) { s_sum[threadIdx.x] = 0.f; s_sq[threadIdx.x] = 0.f; }
    __syncthreads();

    const int warp = threadIdx.x >> 5;
    const int lane = threadIdx.x & 31;
    const int f0 = lane * 2;
    const float ep1 = 1.0f + epsv[l];
    const float bb0 = b1l[f0], bb1 = b1l[f0 + 1];

    float2 psum = make_float2(0.f, 0.f), psq = make_float2(0.f, 0.f);

    for (int n = blockIdx.x * WPB + warp; n < NN; n += gridDim.x * WPB) {
        const int e0 = g_off[n], e1 = g_off[n + 1];
        float accx = 0.f, accy = 0.f;
        for (int eb = e0; eb < e1; eb += 32) {
            int myE = eb + lane;
            int s = 0; float wv = 0.f;
            if (myE < e1) { s = g_esrc[myE]; wv = g_ew[myE]; }
            #pragma unroll
            for (int j = 0; j < 32; j++) {
                int   sj = __shfl_sync(0xffffffffu, s, j);
                float wj = __shfl_sync(0xffffffffu, wv, j);
                float2 hv = *(const float2*)(hin + (size_t)sj * D + f0);
                accx = fmaf(wj, hv.x, accx);
                accy = fmaf(wj, hv.y, accy);
            }
        }
        float2 hn = *(const float2*)(hin + (size_t)n * D + f0);
        srow[warp][f0]     = fmaf(ep1, hn.x, accx);
        srow[warp][f0 + 1] = fmaf(ep1, hn.y, accy);
        __syncwarp();
        float tx = bb0, ty = bb1;
        #pragma unroll
        for (int k = 0; k < D; k++) {
            float hk = srow[warp][k];
            float2 wv2 = *(const float2*)(sW + k * D + f0);
            tx = fmaf(hk, wv2.x, tx);
            ty = fmaf(hk, wv2.y, ty);
        }
        *(float2*)(g_t + (size_t)n * D + f0) = make_float2(tx, ty);
        psum.x += tx; psum.y += ty;
        psq.x = fmaf(tx, tx, psq.x); psq.y = fmaf(ty, ty, psq.y);
        __syncwarp();
    }
    atomicAdd(&s_sum[f0], psum.x);
    atomicAdd(&s_sum[f0 + 1], psum.y);
    atomicAdd(&s_sq[f0], psq.x);
    atomicAdd(&s_sq[f0 + 1], psq.y);
    __syncthreads();
    if (threadIdx.x < D) {
        atomicAdd(&g_stats[(l * 4 + 0) * D + threadIdx.x], s_sum[threadIdx.x]);
        atomicAdd(&g_stats[(l * 4 + 1) * D + threadIdx.x], s_sq[threadIdx.x]);
    }
}

// ---------------- layer stage 2: BN+ReLU + GEMM2 + stats ----------------
__global__ __launch_bounds__(TPB) void k_layer2(
    int l, const float* __restrict__ bng, const float* __restrict__ bnb,
    const float* __restrict__ W2l, const float* __restrict__ b2l)
{
    __shared__ float sW[D * D];
    __shared__ float srow[WPB][D];
    __shared__ float s_sum[D];
    __shared__ float s_sq[D];

    for (int i = threadIdx.x; i < D * D; i += TPB) sW[i] = W2l[i];
    if (threadIdx.x < D) { s_sum[threadIdx.x] = 0.f; s_sq[threadIdx.x] = 0.f; }
    __syncthreads();

    const int warp = threadIdx.x >> 5;
    const int lane = threadIdx.x & 31;
    const int f0 = lane * 2;
    const float invN = 1.0f / NN;
    const float* sum1 = g_stats + (l * 4 + 0) * D;
    const float* sq1  = g_stats + (l * 4 + 1) * D;
    float mu0 = sum1[f0] * invN, mu1 = sum1[f0 + 1] * invN;
    float v0 = sq1[f0] * invN - mu0 * mu0;
    float v1 = sq1[f0 + 1] * invN - mu1 * mu1;
    float sc0 = bng[f0] * rsqrtf(v0 + BN_EPS);
    float sc1 = bng[f0 + 1] * rsqrtf(v1 + BN_EPS);
    float sh0 = bnb[f0] - mu0 * sc0;
    float sh1 = bnb[f0 + 1] - mu1 * sc1;
    const float bb0 = b2l[f0], bb1 = b2l[f0 + 1];

    float2 psum = make_float2(0.f, 0.f), psq = make_float2(0.f, 0.f);

    for (int n = blockIdx.x * WPB + warp; n < NN; n += gridDim.x * WPB) {
        float2 t2 = *(const float2*)(g_t + (size_t)n * D + f0);
        float u0 = fmaxf(fmaf(t2.x, sc0, sh0), 0.f);
        float u1 = fmaxf(fmaf(t2.y, sc1, sh1), 0.f);
        srow[warp][f0] = u0; srow[warp][f0 + 1] = u1;
        __syncwarp();
        float rx = bb0, ry = bb1;
        #pragma unroll
        for (int k = 0; k < D; k++) {
            float hk = srow[warp][k];
            float2 wv2 = *(const float2*)(sW + k * D + f0);
            rx = fmaf(hk, wv2.x, rx);
            ry = fmaf(hk, wv2.y, ry);
        }
        *(float2*)(g_t + (size_t)n * D + f0) = make_float2(rx, ry);
        psum.x += rx; psum.y += ry;
        psq.x = fmaf(rx, rx, psq.x); psq.y = fmaf(ry, ry, psq.y);
        __syncwarp();
    }
    atomicAdd(&s_sum[f0], psum.x);
    atomicAdd(&s_sum[f0 + 1], psum.y);
    atomicAdd(&s_sq[f0], psq.x);
    atomicAdd(&s_sq[f0 + 1], psq.y);
    __syncthreads();
    if (threadIdx.x < D) {
        atomicAdd(&g_stats[(l * 4 + 2) * D + threadIdx.x], s_sum[threadIdx.x]);
        atomicAdd(&g_stats[(l * 4 + 3) * D + threadIdx.x], s_sq[threadIdx.x]);
    }
}

// ---------------- layer stage 3: outer BN + ReLU ----------------
__global__ void k_layer3(int l, const float* __restrict__ bng, const float* __restrict__ bnb)
{
    int idx = blockIdx.x * blockDim.x + threadIdx.x;
    if (idx >= NN * (D / 4)) return;
    int f0 = (idx & (D / 4 - 1)) * 4;
    const float invN = 1.0f / NN;
    const float* sum2 = g_stats + (l * 4 + 2) * D;
    const float* sq2  = g_stats + (l * 4 + 3) * D;
    float4 t = *(const float4*)(g_t + (size_t)idx * 4);
    float tv[4] = {t.x, t.y, t.z, t.w};
    float o[4];
    #pragma unroll
    for (int i = 0; i < 4; i++) {
        float mu = sum2[f0 + i] * invN;
        float var = sq2[f0 + i] * invN - mu * mu;
        float sc = bng[f0 + i] * rsqrtf(var + BN_EPS);
        float sh = bnb[f0 + i] - mu * sc;
        o[i] = fmaxf(fmaf(tv[i], sc, sh), 0.f);
    }
    *(float4*)(g_h + (size_t)idx * 4) = make_float4(o[0], o[1], o[2], o[3]);
}

// ---------------- pooling: block per graph, atomic-free ----------------
__global__ void k_pool(const float* __restrict__ xin, int pidx)
{
    const float* h = (pidx == 0) ? xin : g_h;
    const int g = blockIdx.x;
    const int n0 = g_gstart[g], n1 = g_gstart[g + 1];
    const int warp = threadIdx.x >> 5;
    const int lane = threadIdx.x & 31;
    const int f0 = lane * 2;
    float2 acc = make_float2(0.f, 0.f);
    for (int n = n0 + warp; n < n1; n += 8) {
        float2 v = *(const float2*)(h + (size_t)n * D + f0);
        acc.x += v.x; acc.y += v.y;
    }
    __shared__ float sa[8][D];
    sa[warp][f0] = acc.x;
    sa[warp][f0 + 1] = acc.y;
    __syncthreads();
    if (threadIdx.x < D) {
        float s = 0.f;
        #pragma unroll
        for (int wv = 0; wv < 8; wv++) s += sa[wv][threadIdx.x];
        g_pool[((size_t)pidx * NG + g) * D + threadIdx.x] = s;
    }
}

// ---------------- readout ----------------
__global__ void k_score(const float* __restrict__ predW, const float* __restrict__ predb,
                        float* __restrict__ out)
{
    int idx = blockIdx.x * blockDim.x + threadIdx.x;
    if (idx >= NG * 16) return;
    int g = idx >> 4, o = idx & 15;
    float s = 0.f;
    #pragma unroll
    for (int l = 0; l < NL + 1; l++) {
        s += predb[l * 16 + o];
        const float* P  = g_pool + ((size_t)l * NG + g) * D;
        const float* Wp = predW + (size_t)l * D * 16;
        #pragma unroll
        for (int d = 0; d < D; d++) s = fmaf(P[d], Wp[d * 16 + o], s);
    }
    out[idx] = s;
}

// ---------------- launch ----------------
extern "C" void kernel_launch(void* const* d_in, const int* in_sizes, int n_in,
                              void* d_out, int out_size)
{
    const float* x    = (const float*)d_in[0];
    const float* w    = (const float*)d_in[1];
    const int*   src  = (const int*)d_in[2];
    const int*   dst  = (const int*)d_in[3];
    const int*   gids = (const int*)d_in[4];
    const float* eps  = (const float*)d_in[5];
    const float* W1   = (const float*)d_in[6];
    const float* b1   = (const float*)d_in[7];
    const float* mbng = (const float*)d_in[8];
    const float* mbnb = (const float*)d_in[9];
    const float* W2   = (const float*)d_in[10];
    const float* b2   = (const float*)d_in[11];
    const float* bng  = (const float*)d_in[12];
    const float* bnb  = (const float*)d_in[13];
    const float* predW = (const float*)d_in[14];
    const float* predb = (const float*)d_in[15];
    float* out = (float*)d_out;

    k_init<<<(NN + 255) / 256, 256>>>();
    k_hist<<<(NE + 255) / 256, 256>>>(dst);
    k_gstart<<<1, 256>>>(gids);
    k_scan<<<1, 1024>>>();
    k_scatter<<<(NE + 255) / 256, 256>>>(src, dst, w);
    k_pool<<<NG, 256>>>(x, 0);

    for (int l = 0; l < NL; l++) {
        k_layer1<<<GRID1, TPB>>>(x, l, W1 + (size_t)l * D * D, b1 + (size_t)l * D, eps);
        k_layer2<<<GRID1, TPB>>>(l, mbng + (size_t)l * D, mbnb + (size_t)l * D,
                                 W2 + (size_t)l * D * D, b2 + (size_t)l * D);
        k_layer3<<<(NN * (D / 4) + 255) / 256, 256>>>(l, bng + (size_t)l * D, bnb + (size_t)l * D);
        k_pool<<<NG, 256>>>(x, l + 1);
    }
    k_score<<<(NG * 16 + 255) / 256, 256>>>(predW, predb, out);
}

// round 2
// speedup vs baseline: 1.2770x; 1.2770x over previous
#include <cuda_runtime.h>
#include <cuda_bf16.h>

#define NN 50000
#define NE 800000
#define NG 128
#define D  64
#define NL 4
#define BN_EPS 1e-5f

#define TPB 512
#define WPB 16
#define GRID1 296

#define SCHUNK 512
#define NBSCAN ((NN + SCHUNK - 1) / SCHUNK)   // 98

// ---------------- device scratch (no allocations allowed) ----------------
__device__ int   g_deg[NN];
__device__ int   g_off[NN + 1];
__device__ int   g_cur[NN];
__device__ int   g_esrc[NE];
__device__ float g_ew[NE];
__device__ __align__(16) float g_h[NN * D];   // node features (layer output)
__device__ __align__(16) float g_t[NN * D];   // intermediate t / r buffer
__device__ float g_stats[NL * 4 * D];         // [l][sum1,sq1,sum2,sq2][64]
__device__ float g_pool[(NL + 1) * NG * D];   // pooled per-graph features
__device__ int   g_gstart[NG + 1];
__device__ int   g_bsum[NBSCAN];
__device__ int   g_boff[NBSCAN];

// ---------------- init: zero degree + stats ----------------
__global__ void k_init()
{
    int i = blockIdx.x * blockDim.x + threadIdx.x;
    if (i < NN) g_deg[i] = 0;
    if (i < NL * 4 * D) g_stats[i] = 0.f;
}

// ---------------- CSR build ----------------
__global__ void k_hist(const int* __restrict__ dst)
{
    int e = blockIdx.x * blockDim.x + threadIdx.x;
    if (e < NE) atomicAdd(&g_deg[dst[e]], 1);
}

// pass A: per-chunk sums
__global__ void k_scanA()
{
    __shared__ int red[SCHUNK];
    int t = threadIdx.x;
    int i = blockIdx.x * SCHUNK + t;
    red[t] = (i < NN) ? g_deg[i] : 0;
    __syncthreads();
    for (int s = SCHUNK / 2; s > 0; s >>= 1) {
        if (t < s) red[t] += red[t + s];
        __syncthreads();
    }
    if (t == 0) g_bsum[blockIdx.x] = red[0];
}

// pass B: scan the 98 chunk sums (1 small block)
__global__ void k_scanB()
{
    __shared__ int sv[128];
    int t = threadIdx.x;
    int v = (t < NBSCAN) ? g_bsum[t] : 0;
    sv[t] = v;
    __syncthreads();
    for (int off = 1; off < 128; off <<= 1) {
        int u = (t >= off) ? sv[t - off] : 0;
        __syncthreads();
        sv[t] += u;
        __syncthreads();
    }
    if (t < NBSCAN) g_boff[t] = sv[t] - v;   // exclusive
    if (t == 127) g_off[NN] = sv[127];
}

// pass C: local scan + add chunk offset
__global__ void k_scanC()
{
    __shared__ int sd[SCHUNK];
    int t = threadIdx.x;
    int i = blockIdx.x * SCHUNK + t;
    int d = (i < NN) ? g_deg[i] : 0;
    sd[t] = d;
    __syncthreads();
    for (int off = 1; off < SCHUNK; off <<= 1) {
        int u = (t >= off) ? sd[t - off] : 0;
        __syncthreads();
        sd[t] += u;
        __syncthreads();
    }
    if (i < NN) {
        int excl = sd[t] - d + g_boff[blockIdx.x];
        g_off[i] = excl;
        g_cur[i] = excl;
    }
}

__global__ void k_scatter(const int* __restrict__ src, const int* __restrict__ dst,
                          const float* __restrict__ w)
{
    int e = blockIdx.x * blockDim.x + threadIdx.x;
    if (e < NE) {
        int d = dst[e];
        int p = atomicAdd(&g_cur[d], 1);
        g_esrc[p] = src[e];
        g_ew[p]   = w[e];
    }
}

// ---------------- graph boundaries (graph_ids sorted) ----------------
__global__ void k_gstart(const int* __restrict__ gids)
{
    int g = threadIdx.x;
    if (g > NG) return;
    if (g == NG) { g_gstart[NG] = NN; return; }
    int lo = 0, hi = NN;
    while (lo < hi) {
        int m = (lo + hi) >> 1;
        if (gids[m] < g) lo = m + 1; else hi = m;
    }
    g_gstart[g] = lo;
}

// ---------------- layer stage 1: aggregate + GEMM1 + stats ----------------
__global__ __launch_bounds__(TPB) void k_layer1(
    const float* __restrict__ x, int l,
    const float* __restrict__ W1l, const float* __restrict__ b1l,
    const float* __restrict__ epsv)
{
    __shared__ float sW[D * D];
    __shared__ __align__(16) float srow[WPB][D];
    __shared__ float s_sum[D];
    __shared__ float s_sq[D];

    const float* hin = (l == 0) ? x : g_h;

    for (int i = threadIdx.x; i < D * D; i += TPB) sW[i] = W1l[i];
    if (threadIdx.x < D) { s_sum[threadIdx.x] = 0.f; s_sq[threadIdx.x] = 0.f; }
    __syncthreads();

    const int warp = threadIdx.x >> 5;
    const int lane = threadIdx.x & 31;
    const int grp  = lane >> 4;         // 0/1 : which edge of the pair
    const int f4   = (lane & 15) * 4;   // float4 feature base for gather
    const int f0   = lane * 2;          // 2-feature base for GEMM epilogue
    const float ep1 = 1.0f + epsv[l];
    const float bb0 = b1l[f0], bb1 = b1l[f0 + 1];

    float2 psum = make_float2(0.f, 0.f), psq = make_float2(0.f, 0.f);

    for (int n = blockIdx.x * WPB + warp; n < NN; n += gridDim.x * WPB) {
        const int e0 = g_off[n], e1 = g_off[n + 1];
        float4 acc = make_float4(0.f, 0.f, 0.f, 0.f);
        for (int eb = e0; eb < e1; eb += 32) {
            const int cnt = min(32, e1 - eb);
            int s = 0; float wv = 0.f;
            if (lane < cnt) { s = g_esrc[eb + lane]; wv = g_ew[eb + lane]; }
            for (int t = 0; t < cnt; t += 2) {
                int idx = t + grp;
                int   sj = __shfl_sync(0xffffffffu, s, idx);
                float wj = __shfl_sync(0xffffffffu, wv, idx);
                if (idx < cnt) {
                    float4 hv = *(const float4*)(hin + (size_t)sj * D + f4);
                    acc.x = fmaf(wj, hv.x, acc.x);
                    acc.y = fmaf(wj, hv.y, acc.y);
                    acc.z = fmaf(wj, hv.z, acc.z);
                    acc.w = fmaf(wj, hv.w, acc.w);
                }
            }
        }
        // combine the two edge-groups
        acc.x += __shfl_xor_sync(0xffffffffu, acc.x, 16);
        acc.y += __shfl_xor_sync(0xffffffffu, acc.y, 16);
        acc.z += __shfl_xor_sync(0xffffffffu, acc.z, 16);
        acc.w += __shfl_xor_sync(0xffffffffu, acc.w, 16);
        if (grp == 0) {
            float4 hn = *(const float4*)(hin + (size_t)n * D + f4);
            float4 r;
            r.x = fmaf(ep1, hn.x, acc.x);
            r.y = fmaf(ep1, hn.y, acc.y);
            r.z = fmaf(ep1, hn.z, acc.z);
            r.w = fmaf(ep1, hn.w, acc.w);
            *(float4*)&srow[warp][f4] = r;
        }
        __syncwarp();
        // GEMM1 row
        float tx = bb0, ty = bb1;
        #pragma unroll
        for (int k = 0; k < D; k++) {
            float hk = srow[warp][k];
            float2 wv2 = *(const float2*)(sW + k * D + f0);
            tx = fmaf(hk, wv2.x, tx);
            ty = fmaf(hk, wv2.y, ty);
        }
        *(float2*)(g_t + (size_t)n * D + f0) = make_float2(tx, ty);
        psum.x += tx; psum.y += ty;
        psq.x = fmaf(tx, tx, psq.x); psq.y = fmaf(ty, ty, psq.y);
        __syncwarp();
    }
    atomicAdd(&s_sum[f0], psum.x);
    atomicAdd(&s_sum[f0 + 1], psum.y);
    atomicAdd(&s_sq[f0], psq.x);
    atomicAdd(&s_sq[f0 + 1], psq.y);
    __syncthreads();
    if (threadIdx.x < D) {
        atomicAdd(&g_stats[(l * 4 + 0) * D + threadIdx.x], s_sum[threadIdx.x]);
        atomicAdd(&g_stats[(l * 4 + 1) * D + threadIdx.x], s_sq[threadIdx.x]);
    }
}

// ---------------- layer stage 2: BN+ReLU + GEMM2 + stats ----------------
__global__ __launch_bounds__(TPB) void k_layer2(
    int l, const float* __restrict__ bng, const float* __restrict__ bnb,
    const float* __restrict__ W2l, const float* __restrict__ b2l)
{
    __shared__ float sW[D * D];
    __shared__ float srow[WPB][D];
    __shared__ float s_sum[D];
    __shared__ float s_sq[D];

    for (int i = threadIdx.x; i < D * D; i += TPB) sW[i] = W2l[i];
    if (threadIdx.x < D) { s_sum[threadIdx.x] = 0.f; s_sq[threadIdx.x] = 0.f; }
    __syncthreads();

    const int warp = threadIdx.x >> 5;
    const int lane = threadIdx.x & 31;
    const int f0 = lane * 2;
    const float invN = 1.0f / NN;
    const float* sum1 = g_stats + (l * 4 + 0) * D;
    const float* sq1  = g_stats + (l * 4 + 1) * D;
    float mu0 = sum1[f0] * invN, mu1 = sum1[f0 + 1] * invN;
    float v0 = sq1[f0] * invN - mu0 * mu0;
    float v1 = sq1[f0 + 1] * invN - mu1 * mu1;
    float sc0 = bng[f0] * rsqrtf(v0 + BN_EPS);
    float sc1 = bng[f0 + 1] * rsqrtf(v1 + BN_EPS);
    float sh0 = bnb[f0] - mu0 * sc0;
    float sh1 = bnb[f0 + 1] - mu1 * sc1;
    const float bb0 = b2l[f0], bb1 = b2l[f0 + 1];

    float2 psum = make_float2(0.f, 0.f), psq = make_float2(0.f, 0.f);

    for (int n = blockIdx.x * WPB + warp; n < NN; n += gridDim.x * WPB) {
        float2 t2 = *(const float2*)(g_t + (size_t)n * D + f0);
        float u0 = fmaxf(fmaf(t2.x, sc0, sh0), 0.f);
        float u1 = fmaxf(fmaf(t2.y, sc1, sh1), 0.f);
        srow[warp][f0] = u0; srow[warp][f0 + 1] = u1;
        __syncwarp();
        float rx = bb0, ry = bb1;
        #pragma unroll
        for (int k = 0; k < D; k++) {
            float hk = srow[warp][k];
            float2 wv2 = *(const float2*)(sW + k * D + f0);
            rx = fmaf(hk, wv2.x, rx);
            ry = fmaf(hk, wv2.y, ry);
        }
        *(float2*)(g_t + (size_t)n * D + f0) = make_float2(rx, ry);
        psum.x += rx; psum.y += ry;
        psq.x = fmaf(rx, rx, psq.x); psq.y = fmaf(ry, ry, psq.y);
        __syncwarp();
    }
    atomicAdd(&s_sum[f0], psum.x);
    atomicAdd(&s_sum[f0 + 1], psum.y);
    atomicAdd(&s_sq[f0], psq.x);
    atomicAdd(&s_sq[f0 + 1], psq.y);
    __syncthreads();
    if (threadIdx.x < D) {
        atomicAdd(&g_stats[(l * 4 + 2) * D + threadIdx.x], s_sum[threadIdx.x]);
        atomicAdd(&g_stats[(l * 4 + 3) * D + threadIdx.x], s_sq[threadIdx.x]);
    }
}

// ---------------- layer stage 3: outer BN + ReLU ----------------
__global__ void k_layer3(int l, const float* __restrict__ bng, const float* __restrict__ bnb)
{
    int idx = blockIdx.x * blockDim.x + threadIdx.x;
    if (idx >= NN * (D / 4)) return;
    int f0 = (idx & (D / 4 - 1)) * 4;
    const float invN = 1.0f / NN;
    const float* sum2 = g_stats + (l * 4 + 2) * D;
    const float* sq2  = g_stats + (l * 4 + 3) * D;
    float4 t = *(const float4*)(g_t + (size_t)idx * 4);
    float tv[4] = {t.x, t.y, t.z, t.w};
    float o[4];
    #pragma unroll
    for (int i = 0; i < 4; i++) {
        float mu = sum2[f0 + i] * invN;
        float var = sq2[f0 + i] * invN - mu * mu;
        float sc = bng[f0 + i] * rsqrtf(var + BN_EPS);
        float sh = bnb[f0 + i] - mu * sc;
        o[i] = fmaxf(fmaf(tv[i], sc, sh), 0.f);
    }
    *(float4*)(g_h + (size_t)idx * 4) = make_float4(o[0], o[1], o[2], o[3]);
}

// ---------------- pooling: block per graph, atomic-free ----------------
__global__ void k_pool(const float* __restrict__ xin, int pidx)
{
    const float* h = (pidx == 0) ? xin : g_h;
    const int g = blockIdx.x;
    const int n0 = g_gstart[g], n1 = g_gstart[g + 1];
    const int warp = threadIdx.x >> 5;
    const int lane = threadIdx.x & 31;
    const int f0 = lane * 2;
    float2 acc = make_float2(0.f, 0.f);
    for (int n = n0 + warp; n < n1; n += 8) {
        float2 v = *(const float2*)(h + (size_t)n * D + f0);
        acc.x += v.x; acc.y += v.y;
    }
    __shared__ float sa[8][D];
    sa[warp][f0] = acc.x;
    sa[warp][f0 + 1] = acc.y;
    __syncthreads();
    if (threadIdx.x < D) {
        float s = 0.f;
        #pragma unroll
        for (int wv = 0; wv < 8; wv++) s += sa[wv][threadIdx.x];
        g_pool[((size_t)pidx * NG + g) * D + threadIdx.x] = s;
    }
}

// ---------------- readout ----------------
__global__ void k_score(const float* __restrict__ predW, const float* __restrict__ predb,
                        float* __restrict__ out)
{
    int idx = blockIdx.x * blockDim.x + threadIdx.x;
    if (idx >= NG * 16) return;
    int g = idx >> 4, o = idx & 15;
    float s = 0.f;
    #pragma unroll
    for (int l = 0; l < NL + 1; l++) {
        s += predb[l * 16 + o];
        const float* P  = g_pool + ((size_t)l * NG + g) * D;
        const float* Wp = predW + (size_t)l * D * 16;
        #pragma unroll
        for (int d = 0; d < D; d++) s = fmaf(P[d], Wp[d * 16 + o], s);
    }
    out[idx] = s;
}

// ---------------- launch ----------------
extern "C" void kernel_launch(void* const* d_in, const int* in_sizes, int n_in,
                              void* d_out, int out_size)
{
    const float* x    = (const float*)d_in[0];
    const float* w    = (const float*)d_in[1];
    const int*   src  = (const int*)d_in[2];
    const int*   dst  = (const int*)d_in[3];
    const int*   gids = (const int*)d_in[4];
    const float* eps  = (const float*)d_in[5];
    const float* W1   = (const float*)d_in[6];
    const float* b1   = (const float*)d_in[7];
    const float* mbng = (const float*)d_in[8];
    const float* mbnb = (const float*)d_in[9];
    const float* W2   = (const float*)d_in[10];
    const float* b2   = (const float*)d_in[11];
    const float* bng  = (const float*)d_in[12];
    const float* bnb  = (const float*)d_in[13];
    const float* predW = (const float*)d_in[14];
    const float* predb = (const float*)d_in[15];
    float* out = (float*)d_out;

    k_init<<<(NN + 255) / 256, 256>>>();
    k_hist<<<(NE + 255) / 256, 256>>>(dst);
    k_gstart<<<1, 256>>>(gids);
    k_scanA<<<NBSCAN, SCHUNK>>>();
    k_scanB<<<1, 128>>>();
    k_scanC<<<NBSCAN, SCHUNK>>>();
    k_scatter<<<(NE + 255) / 256, 256>>>(src, dst, w);
    k_pool<<<NG, 256>>>(x, 0);

    for (int l = 0; l < NL; l++) {
        k_layer1<<<GRID1, TPB>>>(x, l, W1 + (size_t)l * D * D, b1 + (size_t)l * D, eps);
        k_layer2<<<GRID1, TPB>>>(l, mbng + (size_t)l * D, mbnb + (size_t)l * D,
                                 W2 + (size_t)l * D * D, b2 + (size_t)l * D);
        k_layer3<<<(NN * (D / 4) + 255) / 256, 256>>>(l, bng + (size_t)l * D, bnb + (size_t)l * D);
        k_pool<<<NG, 256>>>(x, l + 1);
    }
    k_score<<<(NG * 16 + 255) / 256, 256>>>(predW, predb, out);
}

// round 3
// speedup vs baseline: 1.2900x; 1.0102x over previous
#include <cuda_runtime.h>
#include <cuda_bf16.h>

#define NN 50000
#define NE 800000
#define NG 128
#define D  64
#define NL 4
#define BN_EPS 1e-5f

#define TPB 512
#define WPB 16
#define GRID1 296
#define NPW 8                       // nodes per warp work-group
#define NGRP (NN / NPW)             // 6250 (exact)

#define SCHUNK 512
#define NBSCAN ((NN + SCHUNK - 1) / SCHUNK)   // 98

// ---------------- device scratch (no allocations allowed) ----------------
__device__ int   g_deg[NN];
__device__ int   g_off[NN + 1];
__device__ int   g_cur[NN];
__device__ int   g_esrc[NE];
__device__ float g_ew[NE];
__device__ __align__(16) float g_h[NN * D];
__device__ __align__(16) float g_t[NN * D];
__device__ float g_stats[NL * 4 * D];
__device__ float g_pool[(NL + 1) * NG * D];
__device__ int   g_gstart[NG + 1];
__device__ int   g_bsum[NBSCAN];
__device__ int   g_boff[NBSCAN];
__device__ unsigned g_tick[8];      // dynamic tickets: [0..3]=layer1, [4..7]=layer2

// ---------------- init ----------------
__global__ void k_init()
{
    int i = blockIdx.x * blockDim.x + threadIdx.x;
    if (i < NN) g_deg[i] = 0;
    if (i < NL * 4 * D) g_stats[i] = 0.f;
    if (i < 8) g_tick[i] = 0u;
}

// ---------------- CSR build ----------------
__global__ void k_hist(const int* __restrict__ dst)
{
    int e = blockIdx.x * blockDim.x + threadIdx.x;
    if (e < NE) atomicAdd(&g_deg[dst[e]], 1);
}

__global__ void k_scanA()
{
    __shared__ int red[SCHUNK];
    int t = threadIdx.x;
    int i = blockIdx.x * SCHUNK + t;
    red[t] = (i < NN) ? g_deg[i] : 0;
    __syncthreads();
    for (int s = SCHUNK / 2; s > 0; s >>= 1) {
        if (t < s) red[t] += red[t + s];
        __syncthreads();
    }
    if (t == 0) g_bsum[blockIdx.x] = red[0];
}

__global__ void k_scanB()
{
    __shared__ int sv[128];
    int t = threadIdx.x;
    int v = (t < NBSCAN) ? g_bsum[t] : 0;
    sv[t] = v;
    __syncthreads();
    for (int off = 1; off < 128; off <<= 1) {
        int u = (t >= off) ? sv[t - off] : 0;
        __syncthreads();
        sv[t] += u;
        __syncthreads();
    }
    if (t < NBSCAN) g_boff[t] = sv[t] - v;
    if (t == 127) g_off[NN] = sv[127];
}

__global__ void k_scanC()
{
    __shared__ int sd[SCHUNK];
    int t = threadIdx.x;
    int i = blockIdx.x * SCHUNK + t;
    int d = (i < NN) ? g_deg[i] : 0;
    sd[t] = d;
    __syncthreads();
    for (int off = 1; off < SCHUNK; off <<= 1) {
        int u = (t >= off) ? sd[t - off] : 0;
        __syncthreads();
        sd[t] += u;
        __syncthreads();
    }
    if (i < NN) {
        int excl = sd[t] - d + g_boff[blockIdx.x];
        g_off[i] = excl;
        g_cur[i] = excl;
    }
}

__global__ void k_scatter(const int* __restrict__ src, const int* __restrict__ dst,
                          const float* __restrict__ w)
{
    int e = blockIdx.x * blockDim.x + threadIdx.x;
    if (e < NE) {
        int d = dst[e];
        int p = atomicAdd(&g_cur[d], 1);
        g_esrc[p] = src[e];
        g_ew[p]   = w[e];
    }
}

__global__ void k_gstart(const int* __restrict__ gids)
{
    int g = threadIdx.x;
    if (g > NG) return;
    if (g == NG) { g_gstart[NG] = NN; return; }
    int lo = 0, hi = NN;
    while (lo < hi) {
        int m = (lo + hi) >> 1;
        if (gids[m] < g) lo = m + 1; else hi = m;
    }
    g_gstart[g] = lo;
}

// ---------------- layer stage 1: aggregate + GEMM1 + stats ----------------
__global__ __launch_bounds__(TPB) void k_layer1(
    const float* __restrict__ x, int l,
    const float* __restrict__ W1l, const float* __restrict__ b1l,
    const float* __restrict__ epsv)
{
    __shared__ float sW[D * D];
    __shared__ __align__(16) float srow[WPB * NPW * D];   // 32 KB
    __shared__ float s_sum[D];
    __shared__ float s_sq[D];

    const float* hin = (l == 0) ? x : g_h;

    for (int i = threadIdx.x; i < D * D; i += TPB) sW[i] = W1l[i];
    if (threadIdx.x < D) { s_sum[threadIdx.x] = 0.f; s_sq[threadIdx.x] = 0.f; }
    __syncthreads();

    const int warp = threadIdx.x >> 5;
    const int lane = threadIdx.x & 31;
    const int grp  = lane >> 4;
    const int f4   = (lane & 15) * 4;
    const int f0   = lane * 2;
    const float ep1 = 1.0f + epsv[l];
    const float bb0 = b1l[f0], bb1 = b1l[f0 + 1];
    float* myrow = srow + warp * (NPW * D);

    float2 psum = make_float2(0.f, 0.f), psq = make_float2(0.f, 0.f);

    for (;;) {
        unsigned g = 0;
        if (lane == 0) g = atomicAdd(&g_tick[l], 1u);
        g = __shfl_sync(0xffffffffu, g, 0);
        if (g >= NGRP) break;
        const int base = (int)g * NPW;

        // aggregate NPW nodes into shared rows
        #pragma unroll 1
        for (int j = 0; j < NPW; j++) {
            const int n = base + j;
            const int e0 = g_off[n], e1 = g_off[n + 1];
            float4 acc = make_float4(0.f, 0.f, 0.f, 0.f);
            for (int eb = e0; eb < e1; eb += 32) {
                const int cnt = min(32, e1 - eb);
                int s = 0; float wv = 0.f;
                if (lane < cnt) { s = g_esrc[eb + lane]; wv = g_ew[eb + lane]; }
                for (int t = 0; t < cnt; t += 2) {
                    int idx = t + grp;
                    int   sj = __shfl_sync(0xffffffffu, s, idx);
                    float wj = __shfl_sync(0xffffffffu, wv, idx);
                    if (idx < cnt) {
                        float4 hv = *(const float4*)(hin + (size_t)sj * D + f4);
                        acc.x = fmaf(wj, hv.x, acc.x);
                        acc.y = fmaf(wj, hv.y, acc.y);
                        acc.z = fmaf(wj, hv.z, acc.z);
                        acc.w = fmaf(wj, hv.w, acc.w);
                    }
                }
            }
            acc.x += __shfl_xor_sync(0xffffffffu, acc.x, 16);
            acc.y += __shfl_xor_sync(0xffffffffu, acc.y, 16);
            acc.z += __shfl_xor_sync(0xffffffffu, acc.z, 16);
            acc.w += __shfl_xor_sync(0xffffffffu, acc.w, 16);
            if (grp == 0) {
                float4 hn = *(const float4*)(hin + (size_t)n * D + f4);
                float4 r;
                r.x = fmaf(ep1, hn.x, acc.x);
                r.y = fmaf(ep1, hn.y, acc.y);
                r.z = fmaf(ep1, hn.z, acc.z);
                r.w = fmaf(ep1, hn.w, acc.w);
                *(float4*)(myrow + j * D + f4) = r;
            }
        }
        __syncwarp();

        // GEMM1: 8-node register blocking, weights loaded once per 8 nodes
        float a0[NPW], a1[NPW];
        #pragma unroll
        for (int j = 0; j < NPW; j++) { a0[j] = bb0; a1[j] = bb1; }
        #pragma unroll
        for (int k = 0; k < D; k += 4) {
            float2 w0 = *(const float2*)(sW + (k + 0) * D + f0);
            float2 w1 = *(const float2*)(sW + (k + 1) * D + f0);
            float2 w2 = *(const float2*)(sW + (k + 2) * D + f0);
            float2 w3 = *(const float2*)(sW + (k + 3) * D + f0);
            #pragma unroll
            for (int j = 0; j < NPW; j++) {
                float4 h4 = *(const float4*)(myrow + j * D + k);
                a0[j] = fmaf(h4.x, w0.x, a0[j]);
                a0[j] = fmaf(h4.y, w1.x, a0[j]);
                a0[j] = fmaf(h4.z, w2.x, a0[j]);
                a0[j] = fmaf(h4.w, w3.x, a0[j]);
                a1[j] = fmaf(h4.x, w0.y, a1[j]);
                a1[j] = fmaf(h4.y, w1.y, a1[j]);
                a1[j] = fmaf(h4.z, w2.y, a1[j]);
                a1[j] = fmaf(h4.w, w3.y, a1[j]);
            }
        }
        #pragma unroll
        for (int j = 0; j < NPW; j++) {
            *(float2*)(g_t + (size_t)(base + j) * D + f0) = make_float2(a0[j], a1[j]);
            psum.x += a0[j]; psum.y += a1[j];
            psq.x = fmaf(a0[j], a0[j], psq.x);
            psq.y = fmaf(a1[j], a1[j], psq.y);
        }
        __syncwarp();
    }
    atomicAdd(&s_sum[f0], psum.x);
    atomicAdd(&s_sum[f0 + 1], psum.y);
    atomicAdd(&s_sq[f0], psq.x);
    atomicAdd(&s_sq[f0 + 1], psq.y);
    __syncthreads();
    if (threadIdx.x < D) {
        atomicAdd(&g_stats[(l * 4 + 0) * D + threadIdx.x], s_sum[threadIdx.x]);
        atomicAdd(&g_stats[(l * 4 + 1) * D + threadIdx.x], s_sq[threadIdx.x]);
    }
}

// ---------------- layer stage 2: BN+ReLU + GEMM2 + stats ----------------
__global__ __launch_bounds__(TPB) void k_layer2(
    int l, const float* __restrict__ bng, const float* __restrict__ bnb,
    const float* __restrict__ W2l, const float* __restrict__ b2l)
{
    __shared__ float sW[D * D];
    __shared__ __align__(16) float srow[WPB * NPW * D];
    __shared__ float s_sum[D];
    __shared__ float s_sq[D];

    for (int i = threadIdx.x; i < D * D; i += TPB) sW[i] = W2l[i];
    if (threadIdx.x < D) { s_sum[threadIdx.x] = 0.f; s_sq[threadIdx.x] = 0.f; }
    __syncthreads();

    const int warp = threadIdx.x >> 5;
    const int lane = threadIdx.x & 31;
    const int f0 = lane * 2;
    const float invN = 1.0f / NN;
    const float* sum1 = g_stats + (l * 4 + 0) * D;
    const float* sq1  = g_stats + (l * 4 + 1) * D;
    float mu0 = sum1[f0] * invN, mu1 = sum1[f0 + 1] * invN;
    float v0 = sq1[f0] * invN - mu0 * mu0;
    float v1 = sq1[f0 + 1] * invN - mu1 * mu1;
    float sc0 = bng[f0] * rsqrtf(v0 + BN_EPS);
    float sc1 = bng[f0 + 1] * rsqrtf(v1 + BN_EPS);
    float sh0 = bnb[f0] - mu0 * sc0;
    float sh1 = bnb[f0 + 1] - mu1 * sc1;
    const float bb0 = b2l[f0], bb1 = b2l[f0 + 1];
    float* myrow = srow + warp * (NPW * D);

    float2 psum = make_float2(0.f, 0.f), psq = make_float2(0.f, 0.f);

    for (;;) {
        unsigned g = 0;
        if (lane == 0) g = atomicAdd(&g_tick[4 + l], 1u);
        g = __shfl_sync(0xffffffffu, g, 0);
        if (g >= NGRP) break;
        const int base = (int)g * NPW;

        #pragma unroll
        for (int j = 0; j < NPW; j++) {
            float2 t2 = *(const float2*)(g_t + (size_t)(base + j) * D + f0);
            float u0 = fmaxf(fmaf(t2.x, sc0, sh0), 0.f);
            float u1 = fmaxf(fmaf(t2.y, sc1, sh1), 0.f);
            *(float2*)(myrow + j * D + f0) = make_float2(u0, u1);
        }
        __syncwarp();

        float a0[NPW], a1[NPW];
        #pragma unroll
        for (int j = 0; j < NPW; j++) { a0[j] = bb0; a1[j] = bb1; }
        #pragma unroll
        for (int k = 0; k < D; k += 4) {
            float2 w0 = *(const float2*)(sW + (k + 0) * D + f0);
            float2 w1 = *(const float2*)(sW + (k + 1) * D + f0);
            float2 w2 = *(const float2*)(sW + (k + 2) * D + f0);
            float2 w3 = *(const float2*)(sW + (k + 3) * D + f0);
            #pragma unroll
            for (int j = 0; j < NPW; j++) {
                float4 h4 = *(const float4*)(myrow + j * D + k);
                a0[j] = fmaf(h4.x, w0.x, a0[j]);
                a0[j] = fmaf(h4.y, w1.x, a0[j]);
                a0[j] = fmaf(h4.z, w2.x, a0[j]);
                a0[j] = fmaf(h4.w, w3.x, a0[j]);
                a1[j] = fmaf(h4.x, w0.y, a1[j]);
                a1[j] = fmaf(h4.y, w1.y, a1[j]);
                a1[j] = fmaf(h4.z, w2.y, a1[j]);
                a1[j] = fmaf(h4.w, w3.y, a1[j]);
            }
        }
        #pragma unroll
        for (int j = 0; j < NPW; j++) {
            *(float2*)(g_t + (size_t)(base + j) * D + f0) = make_float2(a0[j], a1[j]);
            psum.x += a0[j]; psum.y += a1[j];
            psq.x = fmaf(a0[j], a0[j], psq.x);
            psq.y = fmaf(a1[j], a1[j], psq.y);
        }
        __syncwarp();
    }
    atomicAdd(&s_sum[f0], psum.x);
    atomicAdd(&s_sum[f0 + 1], psum.y);
    atomicAdd(&s_sq[f0], psq.x);
    atomicAdd(&s_sq[f0 + 1], psq.y);
    __syncthreads();
    if (threadIdx.x < D) {
        atomicAdd(&g_stats[(l * 4 + 2) * D + threadIdx.x], s_sum[threadIdx.x]);
        atomicAdd(&g_stats[(l * 4 + 3) * D + threadIdx.x], s_sq[threadIdx.x]);
    }
}

// ---------------- layer stage 3: outer BN + ReLU ----------------
__global__ void k_layer3(int l, const float* __restrict__ bng, const float* __restrict__ bnb)
{
    int idx = blockIdx.x * blockDim.x + threadIdx.x;
    if (idx >= NN * (D / 4)) return;
    int f0 = (idx & (D / 4 - 1)) * 4;
    const float invN = 1.0f / NN;
    const float* sum2 = g_stats + (l * 4 + 2) * D;
    const float* sq2  = g_stats + (l * 4 + 3) * D;
    float4 t = *(const float4*)(g_t + (size_t)idx * 4);
    float tv[4] = {t.x, t.y, t.z, t.w};
    float o[4];
    #pragma unroll
    for (int i = 0; i < 4; i++) {
        float mu = sum2[f0 + i] * invN;
        float var = sq2[f0 + i] * invN - mu * mu;
        float sc = bng[f0 + i] * rsqrtf(var + BN_EPS);
        float sh = bnb[f0 + i] - mu * sc;
        o[i] = fmaxf(fmaf(tv[i], sc, sh), 0.f);
    }
    *(float4*)(g_h + (size_t)idx * 4) = make_float4(o[0], o[1], o[2], o[3]);
}

// ---------------- pooling ----------------
__global__ void k_pool(const float* __restrict__ xin, int pidx)
{
    const float* h = (pidx == 0) ? xin : g_h;
    const int g = blockIdx.x;
    const int n0 = g_gstart[g], n1 = g_gstart[g + 1];
    const int warp = threadIdx.x >> 5;
    const int lane = threadIdx.x & 31;
    const int f0 = lane * 2;
    float2 acc = make_float2(0.f, 0.f);
    for (int n = n0 + warp; n < n1; n += 8) {
        float2 v = *(const float2*)(h + (size_t)n * D + f0);
        acc.x += v.x; acc.y += v.y;
    }
    __shared__ float sa[8][D];
    sa[warp][f0] = acc.x;
    sa[warp][f0 + 1] = acc.y;
    __syncthreads();
    if (threadIdx.x < D) {
        float s = 0.f;
        #pragma unroll
        for (int wv = 0; wv < 8; wv++) s += sa[wv][threadIdx.x];
        g_pool[((size_t)pidx * NG + g) * D + threadIdx.x] = s;
    }
}

// ---------------- readout ----------------
__global__ void k_score(const float* __restrict__ predW, const float* __restrict__ predb,
                        float* __restrict__ out)
{
    int idx = blockIdx.x * blockDim.x + threadIdx.x;
    if (idx >= NG * 16) return;
    int g = idx >> 4, o = idx & 15;
    float s = 0.f;
    #pragma unroll
    for (int l = 0; l < NL + 1; l++) {
        s += predb[l * 16 + o];
        const float* P  = g_pool + ((size_t)l * NG + g) * D;
        const float* Wp = predW + (size_t)l * D * 16;
        #pragma unroll
        for (int d = 0; d < D; d++) s = fmaf(P[d], Wp[d * 16 + o], s);
    }
    out[idx] = s;
}

// ---------------- launch ----------------
extern "C" void kernel_launch(void* const* d_in, const int* in_sizes, int n_in,
                              void* d_out, int out_size)
{
    const float* x    = (const float*)d_in[0];
    const float* w    = (const float*)d_in[1];
    const int*   src  = (const int*)d_in[2];
    const int*   dst  = (const int*)d_in[3];
    const int*   gids = (const int*)d_in[4];
    const float* eps  = (const float*)d_in[5];
    const float* W1   = (const float*)d_in[6];
    const float* b1   = (const float*)d_in[7];
    const float* mbng = (const float*)d_in[8];
    const float* mbnb = (const float*)d_in[9];
    const float* W2   = (const float*)d_in[10];
    const float* b2   = (const float*)d_in[11];
    const float* bng  = (const float*)d_in[12];
    const float* bnb  = (const float*)d_in[13];
    const float* predW = (const float*)d_in[14];
    const float* predb = (const float*)d_in[15];
    float* out = (float*)d_out;

    k_init<<<(NN + 255) / 256, 256>>>();
    k_hist<<<(NE + 255) / 256, 256>>>(dst);
    k_gstart<<<1, 256>>>(gids);
    k_scanA<<<NBSCAN, SCHUNK>>>();
    k_scanB<<<1, 128>>>();
    k_scanC<<<NBSCAN, SCHUNK>>>();
    k_scatter<<<(NE + 255) / 256, 256>>>(src, dst, w);
    k_pool<<<NG, 256>>>(x, 0);

    for (int l = 0; l < NL; l++) {
        k_layer1<<<GRID1, TPB>>>(x, l, W1 + (size_t)l * D * D, b1 + (size_t)l * D, eps);
        k_layer2<<<GRID1, TPB>>>(l, mbng + (size_t)l * D, mbnb + (size_t)l * D,
                                 W2 + (size_t)l * D * D, b2 + (size_t)l * D);
        k_layer3<<<(NN * (D / 4) + 255) / 256, 256>>>(l, bng + (size_t)l * D, bnb + (size_t)l * D);
        k_pool<<<NG, 256>>>(x, l + 1);
    }
    k_score<<<(NG * 16 + 255) / 256, 256>>>(predW, predb, out);
}

// round 4
// speedup vs baseline: 1.7062x; 1.3227x over previous
#include <cuda_runtime.h>

#define NN 50000
#define NE 800000
#define NG 128
#define D  64
#define NL 4
#define BN_EPS 1e-5f

#define NBLK 148
#define TPB  896
#define NWARP (TPB / 32)          // 28
#define GSZ  (NBLK * TPB)
#define NPW  4
#define NGRP (NN / NPW)           // 12500 exact
#define CHK  338                  // ceil(NN / NBLK)

typedef unsigned long long ull;

// ---------------- device scratch ----------------
__device__ int   g_deg[NN];
__device__ int   g_off[NN + 1];
__device__ int   g_cur[NN];
__device__ int   g_esrc[NE];
__device__ float g_ew[NE];
__device__ __align__(16) float g_h[NN * D];
__device__ __align__(16) float g_t[NN * D];
__device__ float g_stats[NL * 4 * D];
__device__ float g_pool[(NL + 1) * NG * D];
__device__ int   g_gstart[NG + 1];
__device__ int   g_bsum[NBLK];
__device__ unsigned g_tick[8];
__device__ unsigned g_barcnt;
__device__ unsigned g_bargen;

// ---------------- f32x2 helpers ----------------
__device__ __forceinline__ ull ffma2(ull a, ull b, ull c) {
    ull d; asm("fma.rn.f32x2 %0, %1, %2, %3;" : "=l"(d) : "l"(a), "l"(b), "l"(c)); return d;
}
__device__ __forceinline__ ull fadd2(ull a, ull b) {
    ull d; asm("add.rn.f32x2 %0, %1, %2;" : "=l"(d) : "l"(a), "l"(b)); return d;
}
__device__ __forceinline__ ull fpack2(float lo, float hi) {
    ull d; asm("mov.b64 %0, {%1, %2};" : "=l"(d) : "f"(lo), "f"(hi)); return d;
}
__device__ __forceinline__ float2 funpack2(ull a) {
    float lo, hi; asm("mov.b64 {%0, %1}, %2;" : "=f"(lo), "=f"(hi) : "l"(a));
    return make_float2(lo, hi);
}

// ---------------- software grid barrier ----------------
__device__ __forceinline__ void gsync() {
    __syncthreads();
    if (threadIdx.x == 0) {
        unsigned gen = *(volatile unsigned*)&g_bargen;
        __threadfence();                         // release my writes
        unsigned t = atomicAdd(&g_barcnt, 1u);
        if (t == NBLK - 1) {
            g_barcnt = 0;
            __threadfence();
            atomicAdd(&g_bargen, 1u);
        } else {
            while (*(volatile unsigned*)&g_bargen == gen) __nanosleep(128);
        }
        __threadfence();                         // acquire (L1 invalidate)
    }
    __syncthreads();
}

// ---------------- graph pooling (block-wide, blocks < NG only) ----------------
__device__ __forceinline__ void pool_block(const float* __restrict__ h, int pidx, int g,
                                           float* scr) {
    const int tid = threadIdx.x, warp = tid >> 5, lane = tid & 31, f0 = lane * 2;
    const int n0 = g_gstart[g], n1 = g_gstart[g + 1];
    float2 acc = make_float2(0.f, 0.f);
    for (int n = n0 + warp; n < n1; n += NWARP) {
        float2 v = *(const float2*)(h + (size_t)n * D + f0);
        acc.x += v.x; acc.y += v.y;
    }
    scr[warp * D + f0] = acc.x;
    scr[warp * D + f0 + 1] = acc.y;
    __syncthreads();
    if (tid < D) {
        float s = 0.f;
        #pragma unroll
        for (int w2 = 0; w2 < NWARP; w2++) s += scr[w2 * D + tid];
        g_pool[((size_t)pidx * NG + g) * D + tid] = s;
    }
    __syncthreads();
}

__global__ __launch_bounds__(TPB, 1) void k_gin(
    const float* __restrict__ x, const float* __restrict__ w,
    const int* __restrict__ src, const int* __restrict__ dst,
    const int* __restrict__ gids, const float* __restrict__ epsv,
    const float* __restrict__ W1, const float* __restrict__ b1,
    const float* __restrict__ mbng, const float* __restrict__ mbnb,
    const float* __restrict__ W2, const float* __restrict__ b2,
    const float* __restrict__ bng, const float* __restrict__ bnb,
    const float* __restrict__ predW, const float* __restrict__ predb,
    float* __restrict__ out)
{
    __shared__ __align__(16) ull   sWp[2048];              // 16 KB (scan overlay)
    __shared__ __align__(16) float srow[NWARP * NPW * D];  // 28 KB (pool overlay)
    __shared__ float s_red[2 * D];                         // 512 B

    const int tid = threadIdx.x, bid = blockIdx.x;
    const int gtid = bid * TPB + tid;
    const int warp = tid >> 5, lane = tid & 31;
    const int grp = lane >> 3, fo = (lane & 7) * 8;
    const int f0 = lane * 2;
    float* myrow = srow + warp * (NPW * D);

    // ---------- phase 0: zero deg/stats/ticks, graph boundaries ----------
    if (gtid < NN) g_deg[gtid] = 0;            // GSZ > NN
    if (gtid < NL * 4 * D) g_stats[gtid] = 0.f;
    if (gtid < 8) g_tick[gtid] = 0u;
    if (bid == 0 && tid <= NG) {
        if (tid == NG) g_gstart[NG] = NN;
        else {
            int lo = 0, hi = NN;
            while (lo < hi) {
                int m = (lo + hi) >> 1;
                if (gids[m] < tid) lo = m + 1; else hi = m;
            }
            g_gstart[tid] = lo;
        }
    }
    gsync();

    // ---------- phase 1: degree histogram ----------
    for (int e = gtid; e < NE; e += GSZ) atomicAdd(&g_deg[dst[e]], 1);
    gsync();

    // ---------- phase 2a: block-local scan ----------
    int* s_scan = (int*)sWp;
    {
        int node = bid * CHK + tid;
        int dv = 0;
        if (tid < CHK && node < NN) dv = g_deg[node];
        if (tid < 512) s_scan[tid] = (tid < CHK) ? dv : 0;
        __syncthreads();
        for (int off = 1; off < 512; off <<= 1) {
            int v = 0;
            if (tid < 512 && tid >= off) v = s_scan[tid - off];
            __syncthreads();
            if (tid < 512) s_scan[tid] += v;
            __syncthreads();
        }
        if (tid < CHK && node < NN) g_off[node] = s_scan[tid] - dv;  // local exclusive
        if (tid == 0) g_bsum[bid] = s_scan[511];
    }
    gsync();

    // ---------- phase 2b: scan block totals, finalize offsets ----------
    {
        int v = 0;
        if (tid < 256) { v = (tid < NBLK) ? g_bsum[tid] : 0; s_scan[tid] = v; }
        __syncthreads();
        for (int off = 1; off < 256; off <<= 1) {
            int u = 0;
            if (tid < 256 && tid >= off) u = s_scan[tid - off];
            __syncthreads();
            if (tid < 256) s_scan[tid] += u;
            __syncthreads();
        }
        if (tid < 256) s_scan[256 + tid] = s_scan[tid] - v;   // exclusive
        __syncthreads();
        int prefix = s_scan[256 + bid];
        int node = bid * CHK + tid;
        if (tid < CHK && node < NN) {
            int o = g_off[node] + prefix;
            g_off[node] = o; g_cur[node] = o;
        }
        if (bid == 0 && tid == 0) g_off[NN] = s_scan[NBLK - 1];
    }
    gsync();

    // ---------- phase 3: scatter edges into CSR + pool0 ----------
    for (int e = gtid; e < NE; e += GSZ) {
        int dn = dst[e];
        int p = atomicAdd(&g_cur[dn], 1);
        g_esrc[p] = src[e];
        g_ew[p] = w[e];
    }
    if (bid < NG) pool_block(x, 0, bid, srow);
    gsync();

    // ---------- layers ----------
    for (int l = 0; l < NL; l++) {
        // ===== phase A: aggregate + GEMM1 + stats1 (+ pool_l for l>0) =====
        {
            const float* W1l = W1 + (size_t)l * D * D;
            for (int i = tid; i < 2048; i += TPB) {
                int k2 = i >> 6, f = i & 63;
                sWp[i] = fpack2(W1l[(2 * k2) * D + f], W1l[(2 * k2 + 1) * D + f]);
            }
            if (tid < 2 * D) s_red[tid] = 0.f;
            __syncthreads();
            if (l > 0 && bid < NG) pool_block(g_h, l, bid, srow);
            __syncthreads();

            const float* hin = (l == 0) ? x : g_h;
            const float ep1 = 1.0f + epsv[l];
            const ull ep2 = fpack2(ep1, ep1);
            float2 bb = *(const float2*)(b1 + (size_t)l * D + f0);
            float2 psum = make_float2(0.f, 0.f), psq = make_float2(0.f, 0.f);

            for (;;) {
                unsigned g = 0;
                if (lane == 0) g = atomicAdd(&g_tick[l], 1u);
                g = __shfl_sync(0xffffffffu, g, 0);
                if (g >= NGRP) break;
                const int base = (int)g * NPW;

                #pragma unroll 1
                for (int j = 0; j < NPW; j++) {
                    const int n = base + j;
                    const int e0 = g_off[n], e1 = g_off[n + 1];
                    ull a0 = 0, a1 = 0, a2 = 0, a3 = 0;
                    for (int eb = e0; eb < e1; eb += 32) {
                        const int cnt = min(32, e1 - eb);
                        int sv = 0; float wv = 0.f;
                        if (lane < cnt) { sv = g_esrc[eb + lane]; wv = g_ew[eb + lane]; }
                        for (int t = 0; t < cnt; t += 4) {
                            int idx = t + grp;
                            int   sj = __shfl_sync(0xffffffffu, sv, idx);
                            float wj = __shfl_sync(0xffffffffu, wv, idx);
                            if (idx < cnt) {
                                const float* hp = hin + (size_t)sj * D + fo;
                                ulonglong2 p0 = *(const ulonglong2*)hp;
                                ulonglong2 p1 = *(const ulonglong2*)(hp + 4);
                                ull w2 = fpack2(wj, wj);
                                a0 = ffma2(p0.x, w2, a0); a1 = ffma2(p0.y, w2, a1);
                                a2 = ffma2(p1.x, w2, a2); a3 = ffma2(p1.y, w2, a3);
                            }
                        }
                    }
                    a0 = fadd2(a0, __shfl_xor_sync(0xffffffffu, a0, 8));
                    a1 = fadd2(a1, __shfl_xor_sync(0xffffffffu, a1, 8));
                    a2 = fadd2(a2, __shfl_xor_sync(0xffffffffu, a2, 8));
                    a3 = fadd2(a3, __shfl_xor_sync(0xffffffffu, a3, 8));
                    a0 = fadd2(a0, __shfl_xor_sync(0xffffffffu, a0, 16));
                    a1 = fadd2(a1, __shfl_xor_sync(0xffffffffu, a1, 16));
                    a2 = fadd2(a2, __shfl_xor_sync(0xffffffffu, a2, 16));
                    a3 = fadd2(a3, __shfl_xor_sync(0xffffffffu, a3, 16));
                    if (grp == 0) {
                        const float* hp = hin + (size_t)n * D + fo;
                        ulonglong2 p0 = *(const ulonglong2*)hp;
                        ulonglong2 p1 = *(const ulonglong2*)(hp + 4);
                        ulonglong2 r0, r1;
                        r0.x = ffma2(p0.x, ep2, a0); r0.y = ffma2(p0.y, ep2, a1);
                        r1.x = ffma2(p1.x, ep2, a2); r1.y = ffma2(p1.y, ep2, a3);
                        *(ulonglong2*)(myrow + j * D + fo) = r0;
                        *(ulonglong2*)(myrow + j * D + fo + 4) = r1;
                    }
                }
                __syncwarp();

                ull acc0[NPW], acc1[NPW];
                #pragma unroll
                for (int j = 0; j < NPW; j++) { acc0[j] = 0; acc1[j] = 0; }
                #pragma unroll
                for (int k2 = 0; k2 < 32; k2++) {
                    ulonglong2 wv2 = *(const ulonglong2*)(sWp + k2 * D + f0);
                    #pragma unroll
                    for (int j = 0; j < NPW; j++) {
                        ull h = *(const ull*)(myrow + j * D + 2 * k2);
                        acc0[j] = ffma2(h, wv2.x, acc0[j]);
                        acc1[j] = ffma2(h, wv2.y, acc1[j]);
                    }
                }
                #pragma unroll
                for (int j = 0; j < NPW; j++) {
                    float2 u0 = funpack2(acc0[j]), u1 = funpack2(acc1[j]);
                    float ax = u0.x + u0.y + bb.x;
                    float ay = u1.x + u1.y + bb.y;
                    *(float2*)(g_t + (size_t)(base + j) * D + f0) = make_float2(ax, ay);
                    psum.x += ax; psum.y += ay;
                    psq.x = fmaf(ax, ax, psq.x);
                    psq.y = fmaf(ay, ay, psq.y);
                }
                __syncwarp();
            }
            atomicAdd(&s_red[f0], psum.x);
            atomicAdd(&s_red[f0 + 1], psum.y);
            atomicAdd(&s_red[D + f0], psq.x);
            atomicAdd(&s_red[D + f0 + 1], psq.y);
            __syncthreads();
            if (tid < D) {
                atomicAdd(&g_stats[(l * 4 + 0) * D + tid], s_red[tid]);
                atomicAdd(&g_stats[(l * 4 + 1) * D + tid], s_red[D + tid]);
            }
        }
        gsync();

        // ===== phase B: BN1 + ReLU + GEMM2 + stats2 =====
        {
            const float* W2l = W2 + (size_t)l * D * D;
            for (int i = tid; i < 2048; i += TPB) {
                int k2 = i >> 6, f = i & 63;
                sWp[i] = fpack2(W2l[(2 * k2) * D + f], W2l[(2 * k2 + 1) * D + f]);
            }
            if (tid < 2 * D) s_red[tid] = 0.f;
            __syncthreads();

            const float invN = 1.0f / NN;
            const float* sum1 = g_stats + (l * 4 + 0) * D;
            const float* sq1  = g_stats + (l * 4 + 1) * D;
            float mu0 = sum1[f0] * invN, mu1 = sum1[f0 + 1] * invN;
            float v0 = sq1[f0] * invN - mu0 * mu0;
            float v1 = sq1[f0 + 1] * invN - mu1 * mu1;
            float sc0 = mbng[l * D + f0] * rsqrtf(v0 + BN_EPS);
            float sc1 = mbng[l * D + f0 + 1] * rsqrtf(v1 + BN_EPS);
            float sh0 = mbnb[l * D + f0] - mu0 * sc0;
            float sh1 = mbnb[l * D + f0 + 1] - mu1 * sc1;
            float2 bb = *(const float2*)(b2 + (size_t)l * D + f0);
            float2 psum = make_float2(0.f, 0.f), psq = make_float2(0.f, 0.f);

            for (;;) {
                unsigned g = 0;
                if (lane == 0) g = atomicAdd(&g_tick[4 + l], 1u);
                g = __shfl_sync(0xffffffffu, g, 0);
                if (g >= NGRP) break;
                const int base = (int)g * NPW;

                #pragma unroll
                for (int j = 0; j < NPW; j++) {
                    float2 t2 = *(const float2*)(g_t + (size_t)(base + j) * D + f0);
                    float u0 = fmaxf(fmaf(t2.x, sc0, sh0), 0.f);
                    float u1 = fmaxf(fmaf(t2.y, sc1, sh1), 0.f);
                    *(float2*)(myrow + j * D + f0) = make_float2(u0, u1);
                }
                __syncwarp();

                ull acc0[NPW], acc1[NPW];
                #pragma unroll
                for (int j = 0; j < NPW; j++) { acc0[j] = 0; acc1[j] = 0; }
                #pragma unroll
                for (int k2 = 0; k2 < 32; k2++) {
                    ulonglong2 wv2 = *(const ulonglong2*)(sWp + k2 * D + f0);
                    #pragma unroll
                    for (int j = 0; j < NPW; j++) {
                        ull h = *(const ull*)(myrow + j * D + 2 * k2);
                        acc0[j] = ffma2(h, wv2.x, acc0[j]);
                        acc1[j] = ffma2(h, wv2.y, acc1[j]);
                    }
                }
                #pragma unroll
                for (int j = 0; j < NPW; j++) {
                    float2 u0 = funpack2(acc0[j]), u1 = funpack2(acc1[j]);
                    float ax = u0.x + u0.y + bb.x;
                    float ay = u1.x + u1.y + bb.y;
                    *(float2*)(g_t + (size_t)(base + j) * D + f0) = make_float2(ax, ay);
                    psum.x += ax; psum.y += ay;
                    psq.x = fmaf(ax, ax, psq.x);
                    psq.y = fmaf(ay, ay, psq.y);
                }
                __syncwarp();
            }
            atomicAdd(&s_red[f0], psum.x);
            atomicAdd(&s_red[f0 + 1], psum.y);
            atomicAdd(&s_red[D + f0], psq.x);
            atomicAdd(&s_red[D + f0 + 1], psq.y);
            __syncthreads();
            if (tid < D) {
                atomicAdd(&g_stats[(l * 4 + 2) * D + tid], s_red[tid]);
                atomicAdd(&g_stats[(l * 4 + 3) * D + tid], s_red[D + tid]);
            }
        }
        gsync();

        // ===== phase C: outer BN + ReLU -> g_h =====
        {
            if (tid < D) {
                const float invN = 1.0f / NN;
                float mu = g_stats[(l * 4 + 2) * D + tid] * invN;
                float var = g_stats[(l * 4 + 3) * D + tid] * invN - mu * mu;
                float sc = bng[l * D + tid] * rsqrtf(var + BN_EPS);
                s_red[tid] = sc;
                s_red[D + tid] = bnb[l * D + tid] - mu * sc;
            }
            __syncthreads();
            for (int i4 = gtid; i4 < NN * (D / 4); i4 += GSZ) {
                int fb = (i4 & 15) * 4;
                float4 t = *(const float4*)(g_t + (size_t)i4 * 4);
                float4 o;
                o.x = fmaxf(fmaf(t.x, s_red[fb + 0], s_red[D + fb + 0]), 0.f);
                o.y = fmaxf(fmaf(t.y, s_red[fb + 1], s_red[D + fb + 1]), 0.f);
                o.z = fmaxf(fmaf(t.z, s_red[fb + 2], s_red[D + fb + 2]), 0.f);
                o.w = fmaxf(fmaf(t.w, s_red[fb + 3], s_red[D + fb + 3]), 0.f);
                *(float4*)(g_h + (size_t)i4 * 4) = o;
            }
        }
        gsync();
    }

    // ---------- final pool ----------
    if (bid < NG) pool_block(g_h, NL, bid, srow);
    gsync();

    // ---------- score ----------
    for (int idx = gtid; idx < NG * 16; idx += GSZ) {
        int g = idx >> 4, o = idx & 15;
        float s = 0.f;
        #pragma unroll
        for (int l = 0; l < NL + 1; l++) {
            s += predb[l * 16 + o];
            const float* P  = g_pool + ((size_t)l * NG + g) * D;
            const float* Wp = predW + (size_t)l * D * 16;
            #pragma unroll
            for (int d = 0; d < D; d++) s = fmaf(P[d], Wp[d * 16 + o], s);
        }
        out[idx] = s;
    }
}

// ---------------- launch ----------------
extern "C" void kernel_launch(void* const* d_in, const int* in_sizes, int n_in,
                              void* d_out, int out_size)
{
    const float* x    = (const float*)d_in[0];
    const float* w    = (const float*)d_in[1];
    const int*   src  = (const int*)d_in[2];
    const int*   dst  = (const int*)d_in[3];
    const int*   gids = (const int*)d_in[4];
    const float* eps  = (const float*)d_in[5];
    const float* W1   = (const float*)d_in[6];
    const float* b1   = (const float*)d_in[7];
    const float* mbng = (const float*)d_in[8];
    const float* mbnb = (const float*)d_in[9];
    const float* W2   = (const float*)d_in[10];
    const float* b2   = (const float*)d_in[11];
    const float* bng  = (const float*)d_in[12];
    const float* bnb  = (const float*)d_in[13];
    const float* predW = (const float*)d_in[14];
    const float* predb = (const float*)d_in[15];
    float* out = (float*)d_out;

    k_gin<<<NBLK, TPB>>>(x, w, src, dst, gids, eps, W1, b1, mbng, mbnb,
                         W2, b2, bng, bnb, predW, predb, out);
}

// round 5
// speedup vs baseline: 1.7147x; 1.0050x over previous
#include <cuda_runtime.h>

#define NN 50000
#define NE 800000
#define NG 128
#define D  64
#define NL 4
#define BN_EPS 1e-5f

#define NBLK 148
#define TPB  896
#define NWARP (TPB / 32)          // 28
#define GSZ  (NBLK * TPB)
#define NPW  4
#define NGRP (NN / NPW)           // 12500 exact
#define CHK  338                  // ceil(NN / NBLK)

typedef unsigned long long ull;

// ---------------- device scratch ----------------
__device__ int   g_deg[NN];
__device__ int   g_off[NN + 1];
__device__ int   g_cur[NN];
__device__ __align__(8) int2 g_edge[NE];      // {src, float_bits(w)}
__device__ __align__(16) float g_h[NN * D];
__device__ __align__(16) float g_t[NN * D];
__device__ float g_stats[NL * 4 * D];
__device__ float g_pool[(NL + 1) * NG * D];
__device__ int   g_gstart[NG + 1];
__device__ int   g_bsum[NBLK];
__device__ unsigned g_tick[8];
__device__ unsigned g_barcnt;
__device__ unsigned g_bargen;

// ---------------- f32x2 helpers ----------------
__device__ __forceinline__ ull ffma2(ull a, ull b, ull c) {
    ull d; asm("fma.rn.f32x2 %0, %1, %2, %3;" : "=l"(d) : "l"(a), "l"(b), "l"(c)); return d;
}
__device__ __forceinline__ ull fadd2(ull a, ull b) {
    ull d; asm("add.rn.f32x2 %0, %1, %2;" : "=l"(d) : "l"(a), "l"(b)); return d;
}
__device__ __forceinline__ ull fpack2(float lo, float hi) {
    ull d; asm("mov.b64 %0, {%1, %2};" : "=l"(d) : "f"(lo), "f"(hi)); return d;
}
__device__ __forceinline__ float2 funpack2(ull a) {
    float lo, hi; asm("mov.b64 {%0, %1}, %2;" : "=f"(lo), "=f"(hi) : "l"(a));
    return make_float2(lo, hi);
}

// ---------------- software grid barrier ----------------
__device__ __forceinline__ void gsync() {
    __syncthreads();
    if (threadIdx.x == 0) {
        unsigned gen = *(volatile unsigned*)&g_bargen;
        __threadfence();
        unsigned t = atomicAdd(&g_barcnt, 1u);
        if (t == NBLK - 1) {
            g_barcnt = 0;
            __threadfence();
            atomicAdd(&g_bargen, 1u);
        } else {
            while (*(volatile unsigned*)&g_bargen == gen) __nanosleep(64);
        }
        __threadfence();
    }
    __syncthreads();
}

// ---------------- graph pooling (block-wide, blocks < NG only) ----------------
__device__ __forceinline__ void pool_block(const float* __restrict__ h, int pidx, int g,
                                           float* scr) {
    const int tid = threadIdx.x, warp = tid >> 5, lane = tid & 31, f0 = lane * 2;
    const int n0 = g_gstart[g], n1 = g_gstart[g + 1];
    float2 acc = make_float2(0.f, 0.f);
    for (int n = n0 + warp; n < n1; n += NWARP) {
        float2 v = *(const float2*)(h + (size_t)n * D + f0);
        acc.x += v.x; acc.y += v.y;
    }
    scr[warp * D + f0] = acc.x;
    scr[warp * D + f0 + 1] = acc.y;
    __syncthreads();
    if (tid < D) {
        float s = 0.f;
        #pragma unroll
        for (int w2 = 0; w2 < NWARP; w2++) s += scr[w2 * D + tid];
        g_pool[((size_t)pidx * NG + g) * D + tid] = s;
    }
    __syncthreads();
}

__global__ __launch_bounds__(TPB, 1) void k_gin(
    const float* __restrict__ x, const float* __restrict__ w,
    const int* __restrict__ src, const int* __restrict__ dst,
    const int* __restrict__ gids, const float* __restrict__ epsv,
    const float* __restrict__ W1, const float* __restrict__ b1,
    const float* __restrict__ mbng, const float* __restrict__ mbnb,
    const float* __restrict__ W2, const float* __restrict__ b2,
    const float* __restrict__ bng, const float* __restrict__ bnb,
    const float* __restrict__ predW, const float* __restrict__ predb,
    float* __restrict__ out)
{
    __shared__ __align__(16) ull   sWp[2048];              // 16 KB (scan overlay)
    __shared__ __align__(16) float srow[NWARP * NPW * D];  // 28 KB (pool overlay)
    __shared__ float s_red[2 * D];

    const int tid = threadIdx.x, bid = blockIdx.x;
    const int gtid = bid * TPB + tid;
    const int warp = tid >> 5, lane = tid & 31;
    const int grp = lane >> 3, fo = (lane & 7) * 8;
    const int f0 = lane * 2;
    float* myrow = srow + warp * (NPW * D);

    // ---------- phase 0 ----------
    if (gtid < NN) g_deg[gtid] = 0;
    if (gtid < NL * 4 * D) g_stats[gtid] = 0.f;
    if (gtid < 8) g_tick[gtid] = 0u;
    if (bid == 0 && tid <= NG) {
        if (tid == NG) g_gstart[NG] = NN;
        else {
            int lo = 0, hi = NN;
            while (lo < hi) {
                int m = (lo + hi) >> 1;
                if (gids[m] < tid) lo = m + 1; else hi = m;
            }
            g_gstart[tid] = lo;
        }
    }
    gsync();

    // ---------- phase 1: degree histogram ----------
    for (int e = gtid; e < NE; e += GSZ) atomicAdd(&g_deg[dst[e]], 1);
    gsync();

    // ---------- phase 2a: block-local scan ----------
    int* s_scan = (int*)sWp;
    {
        int node = bid * CHK + tid;
        int dv = 0;
        if (tid < CHK && node < NN) dv = g_deg[node];
        if (tid < 512) s_scan[tid] = (tid < CHK) ? dv : 0;
        __syncthreads();
        for (int off = 1; off < 512; off <<= 1) {
            int v = 0;
            if (tid < 512 && tid >= off) v = s_scan[tid - off];
            __syncthreads();
            if (tid < 512) s_scan[tid] += v;
            __syncthreads();
        }
        if (tid < CHK && node < NN) g_off[node] = s_scan[tid] - dv;
        if (tid == 0) g_bsum[bid] = s_scan[511];
    }
    gsync();

    // ---------- phase 2b: scan block totals ----------
    {
        int v = 0;
        if (tid < 256) { v = (tid < NBLK) ? g_bsum[tid] : 0; s_scan[tid] = v; }
        __syncthreads();
        for (int off = 1; off < 256; off <<= 1) {
            int u = 0;
            if (tid < 256 && tid >= off) u = s_scan[tid - off];
            __syncthreads();
            if (tid < 256) s_scan[tid] += u;
            __syncthreads();
        }
        if (tid < 256) s_scan[256 + tid] = s_scan[tid] - v;
        __syncthreads();
        int prefix = s_scan[256 + bid];
        int node = bid * CHK + tid;
        if (tid < CHK && node < NN) {
            int o = g_off[node] + prefix;
            g_off[node] = o; g_cur[node] = o;
        }
        if (bid == 0 && tid == 0) g_off[NN] = s_scan[NBLK - 1];
    }
    gsync();

    // ---------- phase 3: scatter edges + pool0 ----------
    for (int e = gtid; e < NE; e += GSZ) {
        int dn = dst[e];
        int p = atomicAdd(&g_cur[dn], 1);
        g_edge[p] = make_int2(src[e], __float_as_int(w[e]));
    }
    if (bid < NG) pool_block(x, 0, bid, srow);
    gsync();

    // ---------- layers ----------
    for (int l = 0; l < NL; l++) {
        // ===== phase A: aggregate + GEMM1 + stats1 (+ pool_l for l>0) =====
        {
            const float* W1l = W1 + (size_t)l * D * D;
            for (int i = tid; i < 2048; i += TPB) {
                int k2 = i >> 6, f = i & 63;
                sWp[i] = fpack2(W1l[(2 * k2) * D + f], W1l[(2 * k2 + 1) * D + f]);
            }
            if (tid < 2 * D) s_red[tid] = 0.f;
            __syncthreads();
            if (l > 0 && bid < NG) pool_block(g_h, l, bid, srow);
            __syncthreads();

            const float* hin = (l == 0) ? x : g_h;
            const float ep1 = 1.0f + epsv[l];
            const ull ep2 = fpack2(ep1, ep1);
            float2 bb = *(const float2*)(b1 + (size_t)l * D + f0);
            float2 psum = make_float2(0.f, 0.f), psq = make_float2(0.f, 0.f);

            for (;;) {
                unsigned g = 0;
                if (lane == 0) g = atomicAdd(&g_tick[l], 1u);
                g = __shfl_sync(0xffffffffu, g, 0);
                if (g >= NGRP) break;
                const int base = (int)g * NPW;

                #pragma unroll 1
                for (int j = 0; j < NPW; j++) {
                    const int n = base + j;
                    const int e0 = g_off[n], e1 = g_off[n + 1];
                    ull a0 = 0, a1 = 0, a2 = 0, a3 = 0;
                    for (int eb = e0; eb < e1; eb += 32) {
                        const int cnt = min(32, e1 - eb);
                        int sv = 0; float wv = 0.f;
                        if (lane < cnt) {
                            int2 ed = g_edge[eb + lane];
                            sv = ed.x; wv = __int_as_float(ed.y);
                        }
                        #pragma unroll 2
                        for (int t = 0; t < cnt; t += 8) {
                            const int iA = t + grp, iB = t + 4 + grp;
                            int   sA = __shfl_sync(0xffffffffu, sv, iA & 31);
                            float wA = __shfl_sync(0xffffffffu, wv, iA & 31);
                            int   sB = __shfl_sync(0xffffffffu, sv, iB & 31);
                            float wB = __shfl_sync(0xffffffffu, wv, iB & 31);
                            const bool pA = iA < cnt, pB = iB < cnt;
                            ulonglong2 q0, q1, r0, r1;
                            if (pA) {
                                const float* hp = hin + (size_t)sA * D + fo;
                                q0 = *(const ulonglong2*)hp;
                                q1 = *(const ulonglong2*)(hp + 4);
                            }
                            if (pB) {
                                const float* hp = hin + (size_t)sB * D + fo;
                                r0 = *(const ulonglong2*)hp;
                                r1 = *(const ulonglong2*)(hp + 4);
                            }
                            if (pA) {
                                ull w2 = fpack2(wA, wA);
                                a0 = ffma2(q0.x, w2, a0); a1 = ffma2(q0.y, w2, a1);
                                a2 = ffma2(q1.x, w2, a2); a3 = ffma2(q1.y, w2, a3);
                            }
                            if (pB) {
                                ull w2 = fpack2(wB, wB);
                                a0 = ffma2(r0.x, w2, a0); a1 = ffma2(r0.y, w2, a1);
                                a2 = ffma2(r1.x, w2, a2); a3 = ffma2(r1.y, w2, a3);
                            }
                        }
                    }
                    a0 = fadd2(a0, __shfl_xor_sync(0xffffffffu, a0, 8));
                    a1 = fadd2(a1, __shfl_xor_sync(0xffffffffu, a1, 8));
                    a2 = fadd2(a2, __shfl_xor_sync(0xffffffffu, a2, 8));
                    a3 = fadd2(a3, __shfl_xor_sync(0xffffffffu, a3, 8));
                    a0 = fadd2(a0, __shfl_xor_sync(0xffffffffu, a0, 16));
                    a1 = fadd2(a1, __shfl_xor_sync(0xffffffffu, a1, 16));
                    a2 = fadd2(a2, __shfl_xor_sync(0xffffffffu, a2, 16));
                    a3 = fadd2(a3, __shfl_xor_sync(0xffffffffu, a3, 16));
                    if (grp == 0) {
                        const float* hp = hin + (size_t)n * D + fo;
                        ulonglong2 p0 = *(const ulonglong2*)hp;
                        ulonglong2 p1 = *(const ulonglong2*)(hp + 4);
                        ulonglong2 r0, r1;
                        r0.x = ffma2(p0.x, ep2, a0); r0.y = ffma2(p0.y, ep2, a1);
                        r1.x = ffma2(p1.x, ep2, a2); r1.y = ffma2(p1.y, ep2, a3);
                        *(ulonglong2*)(myrow + j * D + fo) = r0;
                        *(ulonglong2*)(myrow + j * D + fo + 4) = r1;
                    }
                }
                __syncwarp();

                ull acc0[NPW], acc1[NPW];
                #pragma unroll
                for (int j = 0; j < NPW; j++) { acc0[j] = 0; acc1[j] = 0; }
                #pragma unroll
                for (int k2 = 0; k2 < 32; k2++) {
                    ulonglong2 wv2 = *(const ulonglong2*)(sWp + k2 * D + f0);
                    #pragma unroll
                    for (int j = 0; j < NPW; j++) {
                        ull h = *(const ull*)(myrow + j * D + 2 * k2);
                        acc0[j] = ffma2(h, wv2.x, acc0[j]);
                        acc1[j] = ffma2(h, wv2.y, acc1[j]);
                    }
                }
                #pragma unroll
                for (int j = 0; j < NPW; j++) {
                    float2 u0 = funpack2(acc0[j]), u1 = funpack2(acc1[j]);
                    float ax = u0.x + u0.y + bb.x;
                    float ay = u1.x + u1.y + bb.y;
                    *(float2*)(g_t + (size_t)(base + j) * D + f0) = make_float2(ax, ay);
                    psum.x += ax; psum.y += ay;
                    psq.x = fmaf(ax, ax, psq.x);
                    psq.y = fmaf(ay, ay, psq.y);
                }
                __syncwarp();
            }
            atomicAdd(&s_red[f0], psum.x);
            atomicAdd(&s_red[f0 + 1], psum.y);
            atomicAdd(&s_red[D + f0], psq.x);
            atomicAdd(&s_red[D + f0 + 1], psq.y);
            __syncthreads();
            if (tid < D) {
                atomicAdd(&g_stats[(l * 4 + 0) * D + tid], s_red[tid]);
                atomicAdd(&g_stats[(l * 4 + 1) * D + tid], s_red[D + tid]);
            }
        }
        gsync();

        // ===== phase B: BN1 + ReLU + GEMM2 + stats2 =====
        {
            const float* W2l = W2 + (size_t)l * D * D;
            for (int i = tid; i < 2048; i += TPB) {
                int k2 = i >> 6, f = i & 63;
                sWp[i] = fpack2(W2l[(2 * k2) * D + f], W2l[(2 * k2 + 1) * D + f]);
            }
            if (tid < 2 * D) s_red[tid] = 0.f;
            __syncthreads();

            const float invN = 1.0f / NN;
            const float* sum1 = g_stats + (l * 4 + 0) * D;
            const float* sq1  = g_stats + (l * 4 + 1) * D;
            float mu0 = sum1[f0] * invN, mu1 = sum1[f0 + 1] * invN;
            float v0 = sq1[f0] * invN - mu0 * mu0;
            float v1 = sq1[f0 + 1] * invN - mu1 * mu1;
            float sc0 = mbng[l * D + f0] * rsqrtf(v0 + BN_EPS);
            float sc1 = mbng[l * D + f0 + 1] * rsqrtf(v1 + BN_EPS);
            float sh0 = mbnb[l * D + f0] - mu0 * sc0;
            float sh1 = mbnb[l * D + f0 + 1] - mu1 * sc1;
            float2 bb = *(const float2*)(b2 + (size_t)l * D + f0);
            float2 psum = make_float2(0.f, 0.f), psq = make_float2(0.f, 0.f);

            for (;;) {
                unsigned g = 0;
                if (lane == 0) g = atomicAdd(&g_tick[4 + l], 1u);
                g = __shfl_sync(0xffffffffu, g, 0);
                if (g >= NGRP) break;
                const int base = (int)g * NPW;

                #pragma unroll
                for (int j = 0; j < NPW; j++) {
                    float2 t2 = *(const float2*)(g_t + (size_t)(base + j) * D + f0);
                    float u0 = fmaxf(fmaf(t2.x, sc0, sh0), 0.f);
                    float u1 = fmaxf(fmaf(t2.y, sc1, sh1), 0.f);
                    *(float2*)(myrow + j * D + f0) = make_float2(u0, u1);
                }
                __syncwarp();

                ull acc0[NPW], acc1[NPW];
                #pragma unroll
                for (int j = 0; j < NPW; j++) { acc0[j] = 0; acc1[j] = 0; }
                #pragma unroll
                for (int k2 = 0; k2 < 32; k2++) {
                    ulonglong2 wv2 = *(const ulonglong2*)(sWp + k2 * D + f0);
                    #pragma unroll
                    for (int j = 0; j < NPW; j++) {
                        ull h = *(const ull*)(myrow + j * D + 2 * k2);
                        acc0[j] = ffma2(h, wv2.x, acc0[j]);
                        acc1[j] = ffma2(h, wv2.y, acc1[j]);
                    }
                }
                #pragma unroll
                for (int j = 0; j < NPW; j++) {
                    float2 u0 = funpack2(acc0[j]), u1 = funpack2(acc1[j]);
                    float ax = u0.x + u0.y + bb.x;
                    float ay = u1.x + u1.y + bb.y;
                    *(float2*)(g_t + (size_t)(base + j) * D + f0) = make_float2(ax, ay);
                    psum.x += ax; psum.y += ay;
                    psq.x = fmaf(ax, ax, psq.x);
                    psq.y = fmaf(ay, ay, psq.y);
                }
                __syncwarp();
            }
            atomicAdd(&s_red[f0], psum.x);
            atomicAdd(&s_red[f0 + 1], psum.y);
            atomicAdd(&s_red[D + f0], psq.x);
            atomicAdd(&s_red[D + f0 + 1], psq.y);
            __syncthreads();
            if (tid < D) {
                atomicAdd(&g_stats[(l * 4 + 2) * D + tid], s_red[tid]);
                atomicAdd(&g_stats[(l * 4 + 3) * D + tid], s_red[D + tid]);
            }
        }
        gsync();

        // ===== phase C: outer BN + ReLU -> g_h =====
        {
            if (tid < D) {
                const float invN = 1.0f / NN;
                float mu = g_stats[(l * 4 + 2) * D + tid] * invN;
                float var = g_stats[(l * 4 + 3) * D + tid] * invN - mu * mu;
                float sc = bng[l * D + tid] * rsqrtf(var + BN_EPS);
                s_red[tid] = sc;
                s_red[D + tid] = bnb[l * D + tid] - mu * sc;
            }
            __syncthreads();
            for (int i4 = gtid; i4 < NN * (D / 4); i4 += GSZ) {
                int fb = (i4 & 15) * 4;
                float4 t = *(const float4*)(g_t + (size_t)i4 * 4);
                float4 o;
                o.x = fmaxf(fmaf(t.x, s_red[fb + 0], s_red[D + fb + 0]), 0.f);
                o.y = fmaxf(fmaf(t.y, s_red[fb + 1], s_red[D + fb + 1]), 0.f);
                o.z = fmaxf(fmaf(t.z, s_red[fb + 2], s_red[D + fb + 2]), 0.f);
                o.w = fmaxf(fmaf(t.w, s_red[fb + 3], s_red[D + fb + 3]), 0.f);
                *(float4*)(g_h + (size_t)i4 * 4) = o;
            }
        }
        gsync();
    }

    // ---------- final pool ----------
    if (bid < NG) pool_block(g_h, NL, bid, srow);
    gsync();

    // ---------- score ----------
    for (int idx = gtid; idx < NG * 16; idx += GSZ) {
        int g = idx >> 4, o = idx & 15;
        float s = 0.f;
        #pragma unroll
        for (int l = 0; l < NL + 1; l++) {
            s += predb[l * 16 + o];
            const float* P  = g_pool + ((size_t)l * NG + g) * D;
            const float* Wp = predW + (size_t)l * D * 16;
            #pragma unroll
            for (int d = 0; d < D; d++) s = fmaf(P[d], Wp[d * 16 + o], s);
        }
        out[idx] = s;
    }
}

// ---------------- launch ----------------
extern "C" void kernel_launch(void* const* d_in, const int* in_sizes, int n_in,
                              void* d_out, int out_size)
{
    const float* x    = (const float*)d_in[0];
    const float* w    = (const float*)d_in[1];
    const int*   src  = (const int*)d_in[2];
    const int*   dst  = (const int*)d_in[3];
    const int*   gids = (const int*)d_in[4];
    const float* eps  = (const float*)d_in[5];
    const float* W1   = (const float*)d_in[6];
    const float* b1   = (const float*)d_in[7];
    const float* mbng = (const float*)d_in[8];
    const float* mbnb = (const float*)d_in[9];
    const float* W2   = (const float*)d_in[10];
    const float* b2   = (const float*)d_in[11];
    const float* bng  = (const float*)d_in[12];
    const float* bnb  = (const float*)d_in[13];
    const float* predW = (const float*)d_in[14];
    const float* predb = (const float*)d_in[15];
    float* out = (float*)d_out;

    k_gin<<<NBLK, TPB>>>(x, w, src, dst, gids, eps, W1, b1, mbng, mbnb,
                         W2, b2, bng, bnb, predW, predb, out);
}